// round 3
// baseline (speedup 1.0000x reference)
#include <cuda_runtime.h>
#include <cstdint>

#define Tt   2048
#define Hd   2048
#define Ee   32
#define DF   1024
#define DS   4096
#define TOPK 6
#define NGROUP 8
#define GSZ  4
#define TKG  4
#define SCALEF 2.5f

// ---------------- static device scratch (no allocations allowed) ----------------
__device__ float g_combine[Tt * Ee];                 // dense combine weights
__device__ int   g_cnt[Ee];                          // tokens per expert
__device__ int   g_off[Ee];                          // exclusive prefix of g_cnt
__device__ int   g_tok[Ee * Tt];                     // per-expert token lists (strided)
__device__ float g_act[(size_t)Tt * TOPK * DF];      // routed up output (compact, 50MB)
__device__ float g_s1[(size_t)Tt * DS];              // shared expert intermediate (33.5MB)

// ---------------- small kernels ----------------
__global__ void zero_cnt_kernel() {
    if (threadIdx.x < Ee) g_cnt[threadIdx.x] = 0;
}

__global__ void offs_kernel() {
    if (threadIdx.x == 0) {
        int r = 0;
        for (int e = 0; e < Ee; e++) { g_off[e] = r; r += g_cnt[e]; }
    }
}

// ---------------- router: one block (128 thr) per token ----------------
__global__ void router_kernel(const float* __restrict__ x,
                              const float* __restrict__ rw,
                              const float* __restrict__ rb) {
    __shared__ __align__(16) float xs[Hd];
    __shared__ float logits[Ee];
    const int t   = blockIdx.x;
    const int tid = threadIdx.x;
    const float* xt = x + (size_t)t * Hd;

    for (int i = tid; i < Hd / 4; i += 128)
        ((float4*)xs)[i] = ((const float4*)xt)[i];
    __syncthreads();

    const int lane = tid & 31, wid = tid >> 5;
    for (int ei = 0; ei < 8; ei++) {
        int e = wid * 8 + ei;
        const float4* wr = (const float4*)(rw + (size_t)e * Hd);
        float s = 0.f;
        for (int i = lane; i < Hd / 4; i += 32) {
            float4 a = ((const float4*)xs)[i];
            float4 b = wr[i];
            s += a.x * b.x + a.y * b.y + a.z * b.z + a.w * b.w;
        }
        #pragma unroll
        for (int o = 16; o; o >>= 1) s += __shfl_xor_sync(0xffffffffu, s, o);
        if (lane == 0) logits[e] = s;
    }
    __syncthreads();

    if (tid < Ee) g_combine[t * Ee + tid] = 0.f;   // zero the dense row first
    __syncthreads();

    if (tid == 0) {
        float sc[Ee], sfc[Ee];
        for (int e = 0; e < Ee; e++) {
            float v = 1.f / (1.f + expf(-logits[e]));
            sc[e]  = v;
            sfc[e] = v + rb[e];
        }
        float gs[NGROUP];
        for (int g = 0; g < NGROUP; g++) {
            float m1 = -1e30f, m2 = -1e30f;
            for (int j = 0; j < GSZ; j++) {
                float v = sfc[g * GSZ + j];
                if (v > m1) { m2 = m1; m1 = v; }
                else if (v > m2) m2 = v;
            }
            gs[g] = m1 + m2;
        }
        bool gsel[NGROUP];
        for (int g = 0; g < NGROUP; g++) gsel[g] = false;
        for (int k = 0; k < TKG; k++) {            // top-4 groups (ties -> lowest idx)
            int bi = -1; float bv = -1e30f;
            for (int g = 0; g < NGROUP; g++)
                if (!gsel[g] && gs[g] > bv) { bv = gs[g]; bi = g; }
            gsel[bi] = true;
        }
        float masked[Ee];
        for (int e = 0; e < Ee; e++) masked[e] = gsel[e / GSZ] ? sfc[e] : 0.0f;

        int   idx[TOPK]; float tw[TOPK]; float tsum = 0.f;
        for (int k = 0; k < TOPK; k++) {
            int bi = 0; float bv = -1e30f;
            for (int e = 0; e < Ee; e++)
                if (masked[e] > bv) { bv = masked[e]; bi = e; }
            masked[bi] = -1e30f;
            idx[k] = bi; tw[k] = sc[bi]; tsum += sc[bi];
        }
        float inv = SCALEF / (tsum + 1e-20f);
        for (int k = 0; k < TOPK; k++) {
            int e = idx[k];
            g_combine[t * Ee + e] = tw[k] * inv;
            int slot = atomicAdd(&g_cnt[e], 1);
            g_tok[e * Tt + slot] = t;
        }
    }
}

// ---------------- tf32 warp-mma GEMM ----------------
#define BM 128
#define BN 128
#define BK 32
#define ASTR 36     // (4m+k) banks -> conflict-free A frag reads
#define BSTR 136    // (8k+n) banks -> conflict-free B frag reads

__device__ __forceinline__ uint32_t f2tf32(float f) {
    uint32_t r;
    asm("cvt.rna.tf32.f32 %0, %1;" : "=r"(r) : "f"(f));
    return r;
}

__device__ __forceinline__ void mma_tf32(float (&c)[4], const uint32_t (&a)[4],
                                         const uint32_t (&b)[2]) {
    asm volatile(
        "mma.sync.aligned.m16n8k8.row.col.f32.tf32.tf32.f32 "
        "{%0,%1,%2,%3}, {%4,%5,%6,%7}, {%8,%9}, {%0,%1,%2,%3};\n"
        : "+f"(c[0]), "+f"(c[1]), "+f"(c[2]), "+f"(c[3])
        : "r"(a[0]), "r"(a[1]), "r"(a[2]), "r"(a[3]), "r"(b[0]), "r"(b[1]));
}

__device__ __forceinline__ void compute_tile(const float* As, const float* Bs,
                                             float (&acc)[2][8][4],
                                             int lane, int mb, int nb) {
    const uint32_t* Asu = (const uint32_t*)As;
    const uint32_t* Bsu = (const uint32_t*)Bs;
    const int qr = lane >> 2, qc = lane & 3;
    #pragma unroll
    for (int ks = 0; ks < BK; ks += 8) {
        uint32_t a[2][4];
        #pragma unroll
        for (int mt = 0; mt < 2; mt++) {
            int r = mb + mt * 16 + qr;
            int kc = ks + qc;
            a[mt][0] = Asu[r * ASTR + kc];
            a[mt][1] = Asu[(r + 8) * ASTR + kc];
            a[mt][2] = Asu[r * ASTR + kc + 4];
            a[mt][3] = Asu[(r + 8) * ASTR + kc + 4];
        }
        uint32_t b[8][2];
        #pragma unroll
        for (int nt = 0; nt < 8; nt++) {
            int n = nb + nt * 8 + qr;
            int kk = ks + qc;
            b[nt][0] = Bsu[kk * BSTR + n];
            b[nt][1] = Bsu[(kk + 4) * BSTR + n];
        }
        #pragma unroll
        for (int mt = 0; mt < 2; mt++)
            #pragma unroll
            for (int nt = 0; nt < 8; nt++)
                mma_tf32(acc[mt][nt], a[mt], b[nt]);
    }
}

// MODE 0: shared up   (A = x,        B = shared_up,   C = g_s1,  relu2)
// MODE 1: shared down (A = g_s1,     B = shared_down, C = out,   plain store)
// MODE 2: moe up      (A = x gather, B = w_up[e],     C = g_act, relu2*combine)
// MODE 3: moe down    (A = g_act,    B = w_down[e],   C = out,   atomic scatter)
template <int MODE>
__global__ __launch_bounds__(256)
void gemm_kernel(const float* __restrict__ Aglob, const float* __restrict__ Bglob,
                 float* __restrict__ Cglob) {
    __shared__ __align__(16) float As[BM * ASTR];
    __shared__ __align__(16) float Bs[BK * BSTR];

    constexpr int Kk = (MODE == 1) ? DS : ((MODE == 3) ? DF : Hd);
    constexpr int Nn = (MODE == 0) ? DS : ((MODE == 2) ? DF : Hd);

    const int tid = threadIdx.x;
    const int e  = (MODE >= 2) ? blockIdx.z : 0;
    const int m0 = blockIdx.y * BM;
    const int n0 = blockIdx.x * BN;

    int ne = Tt, off_e = 0;
    const float* Ap = Aglob;
    const float* Bp = Bglob;
    if (MODE == 1) Ap = g_s1;
    if (MODE == 3) Ap = g_act;
    if (MODE >= 2) {
        ne = g_cnt[e];
        if (m0 >= ne) return;
        off_e = g_off[e];
        Bp = Bglob + (size_t)e * Kk * Nn;
    }

    // -------- loader mapping --------
    int arow[4], acol[4];
    const float* aptr[4];
    #pragma unroll
    for (int i = 0; i < 4; i++) {
        int idx = tid + i * 256;
        int r   = idx >> 3;
        int c4  = (idx & 7) * 4;
        arow[i] = r; acol[i] = c4;
        int grow;
        if (MODE == 2)      grow = (m0 + r < ne) ? g_tok[e * Tt + m0 + r] : -1;
        else if (MODE == 3) grow = (m0 + r < ne) ? (off_e + m0 + r) : -1;
        else                grow = m0 + r;
        aptr[i] = (grow >= 0) ? (Ap + (size_t)grow * Kk + c4) : nullptr;
    }
    int brow[4], bcol[4];
    const float* bptr[4];
    #pragma unroll
    for (int i = 0; i < 4; i++) {
        int idx = tid + i * 256;
        brow[i] = idx >> 5;
        bcol[i] = (idx & 31) * 4;
        bptr[i] = Bp + (size_t)brow[i] * Nn + n0 + bcol[i];
    }

    const int lane = tid & 31, wid = tid >> 5;
    const int mb = (wid >> 1) * 32, nb = (wid & 1) * 64;

    float acc[2][8][4];
    #pragma unroll
    for (int mt = 0; mt < 2; mt++)
        #pragma unroll
        for (int nt = 0; nt < 8; nt++)
            #pragma unroll
            for (int j = 0; j < 4; j++) acc[mt][nt][j] = 0.f;

    float4 ar[4], br[4];

    // prologue load
    #pragma unroll
    for (int i = 0; i < 4; i++)
        ar[i] = aptr[i] ? *(const float4*)(aptr[i]) : make_float4(0.f, 0.f, 0.f, 0.f);
    #pragma unroll
    for (int i = 0; i < 4; i++)
        br[i] = *(const float4*)(bptr[i]);

    const int nk = Kk / BK;
    for (int kb = 0; kb < nk; kb++) {
        // store regs -> smem (tf32 convert amortized here)
        #pragma unroll
        for (int i = 0; i < 4; i++) {
            uint4 u;
            u.x = f2tf32(ar[i].x); u.y = f2tf32(ar[i].y);
            u.z = f2tf32(ar[i].z); u.w = f2tf32(ar[i].w);
            *(uint4*)&As[arow[i] * ASTR + acol[i]] = u;
        }
        #pragma unroll
        for (int i = 0; i < 4; i++) {
            uint4 u;
            u.x = f2tf32(br[i].x); u.y = f2tf32(br[i].y);
            u.z = f2tf32(br[i].z); u.w = f2tf32(br[i].w);
            *(uint4*)&Bs[brow[i] * BSTR + bcol[i]] = u;
        }
        __syncthreads();

        // prefetch next tile while computing this one
        if (kb + 1 < nk) {
            int k0 = (kb + 1) * BK;
            #pragma unroll
            for (int i = 0; i < 4; i++)
                ar[i] = aptr[i] ? *(const float4*)(aptr[i] + k0)
                                : make_float4(0.f, 0.f, 0.f, 0.f);
            #pragma unroll
            for (int i = 0; i < 4; i++)
                br[i] = *(const float4*)(bptr[i] + (size_t)k0 * Nn);
        }

        compute_tile(As, Bs, acc, lane, mb, nb);
        __syncthreads();
    }

    // -------- epilogue --------
    const int qr = lane >> 2, qc = lane & 3;
    #pragma unroll
    for (int mt = 0; mt < 2; mt++) {
        int rl0 = mb + mt * 16 + qr;
        int rl1 = rl0 + 8;
        if (MODE == 0 || MODE == 1) {
            int r0 = m0 + rl0, r1 = m0 + rl1;
            float* Cb = (MODE == 0) ? g_s1 : Cglob;
            #pragma unroll
            for (int nt = 0; nt < 8; nt++) {
                int c = n0 + nb + nt * 8 + qc * 2;
                float v0 = acc[mt][nt][0], v1 = acc[mt][nt][1];
                float v2 = acc[mt][nt][2], v3 = acc[mt][nt][3];
                if (MODE == 0) {
                    v0 = fmaxf(v0, 0.f); v0 *= v0;
                    v1 = fmaxf(v1, 0.f); v1 *= v1;
                    v2 = fmaxf(v2, 0.f); v2 *= v2;
                    v3 = fmaxf(v3, 0.f); v3 *= v3;
                }
                *(float2*)&Cb[(size_t)r0 * Nn + c] = make_float2(v0, v1);
                *(float2*)&Cb[(size_t)r1 * Nn + c] = make_float2(v2, v3);
            }
        } else if (MODE == 2) {
            bool va = (m0 + rl0) < ne, vb = (m0 + rl1) < ne;
            int tk0 = va ? g_tok[e * Tt + m0 + rl0] : 0;
            int tk1 = vb ? g_tok[e * Tt + m0 + rl1] : 0;
            float w0 = va ? g_combine[tk0 * Ee + e] : 0.f;
            float w1 = vb ? g_combine[tk1 * Ee + e] : 0.f;
            size_t cr0 = (size_t)(off_e + m0 + rl0) * DF;
            size_t cr1 = (size_t)(off_e + m0 + rl1) * DF;
            #pragma unroll
            for (int nt = 0; nt < 8; nt++) {
                int c = n0 + nb + nt * 8 + qc * 2;
                float v0 = fmaxf(acc[mt][nt][0], 0.f); v0 = v0 * v0 * w0;
                float v1 = fmaxf(acc[mt][nt][1], 0.f); v1 = v1 * v1 * w0;
                float v2 = fmaxf(acc[mt][nt][2], 0.f); v2 = v2 * v2 * w1;
                float v3 = fmaxf(acc[mt][nt][3], 0.f); v3 = v3 * v3 * w1;
                if (va) *(float2*)&g_act[cr0 + c] = make_float2(v0, v1);
                if (vb) *(float2*)&g_act[cr1 + c] = make_float2(v2, v3);
            }
        } else {  // MODE 3: atomic scatter into out
            bool va = (m0 + rl0) < ne, vb = (m0 + rl1) < ne;
            int tk0 = va ? g_tok[e * Tt + m0 + rl0] : 0;
            int tk1 = vb ? g_tok[e * Tt + m0 + rl1] : 0;
            #pragma unroll
            for (int nt = 0; nt < 8; nt++) {
                int c = n0 + nb + nt * 8 + qc * 2;
                if (va) {
                    atomicAdd(&Cglob[(size_t)tk0 * Hd + c],     acc[mt][nt][0]);
                    atomicAdd(&Cglob[(size_t)tk0 * Hd + c + 1], acc[mt][nt][1]);
                }
                if (vb) {
                    atomicAdd(&Cglob[(size_t)tk1 * Hd + c],     acc[mt][nt][2]);
                    atomicAdd(&Cglob[(size_t)tk1 * Hd + c + 1], acc[mt][nt][3]);
                }
            }
        }
    }
}

// ---------------- launch ----------------
extern "C" void kernel_launch(void* const* d_in, const int* in_sizes, int n_in,
                              void* d_out, int out_size) {
    const float* x     = (const float*)d_in[0];
    const float* rw    = (const float*)d_in[1];
    const float* rb    = (const float*)d_in[2];
    const float* w_up  = (const float*)d_in[3];
    const float* w_dn  = (const float*)d_in[4];
    const float* s_up  = (const float*)d_in[5];
    const float* s_dn  = (const float*)d_in[6];
    float* out = (float*)d_out;

    zero_cnt_kernel<<<1, 32>>>();
    router_kernel<<<Tt, 128>>>(x, rw, rb);
    offs_kernel<<<1, 32>>>();

    // routed up: per-expert gathered GEMM -> g_act
    gemm_kernel<2><<<dim3(DF / BN, Tt / BM, Ee), 256>>>(x, w_up, nullptr);

    // shared expert
    gemm_kernel<0><<<dim3(DS / BN, Tt / BM, 1), 256>>>(x, s_up, nullptr);
    gemm_kernel<1><<<dim3(Hd / BN, Tt / BM, 1), 256>>>(nullptr, s_dn, out);

    // routed down: atomic scatter onto out (after shared wrote it)
    gemm_kernel<3><<<dim3(Hd / BN, Tt / BM, Ee), 256>>>(nullptr, w_dn, out);
}

// round 5
// speedup vs baseline: 1.2113x; 1.2113x over previous
#include <cuda_runtime.h>
#include <cstdint>

#define Tt   2048
#define Hd   2048
#define Ee   32
#define DF   1024
#define DS   4096
#define TOPK 6
#define NGROUP 8
#define GSZ  4
#define TKG  4
#define SCALEF 2.5f

// ---------------- static device scratch (no allocations allowed) ----------------
__device__ float g_combine[Tt * Ee];                 // dense combine weights
__device__ int   g_cnt[Ee];                          // tokens per expert
__device__ int   g_off[Ee];                          // exclusive prefix of g_cnt
__device__ int   g_tok[Ee * Tt];                     // per-expert token lists (strided)
__device__ float g_act[(size_t)Tt * TOPK * DF];      // routed up output (compact)
__device__ float g_s1[(size_t)Tt * DS];              // shared expert intermediate

// ---------------- small kernels ----------------
__global__ void zero_cnt_kernel() {
    if (threadIdx.x < Ee) g_cnt[threadIdx.x] = 0;
}

__global__ void offs_kernel() {
    if (threadIdx.x == 0) {
        int r = 0;
        for (int e = 0; e < Ee; e++) { g_off[e] = r; r += g_cnt[e]; }
    }
}

// ---------------- router: one block (128 thr) per token ----------------
__global__ void router_kernel(const float* __restrict__ x,
                              const float* __restrict__ rw,
                              const float* __restrict__ rb) {
    __shared__ __align__(16) float xs[Hd];
    __shared__ float logits[Ee];
    const int t   = blockIdx.x;
    const int tid = threadIdx.x;
    const float* xt = x + (size_t)t * Hd;

    for (int i = tid; i < Hd / 4; i += 128)
        ((float4*)xs)[i] = ((const float4*)xt)[i];
    __syncthreads();

    const int lane = tid & 31, wid = tid >> 5;
    for (int ei = 0; ei < 8; ei++) {
        int e = wid * 8 + ei;
        const float4* wr = (const float4*)(rw + (size_t)e * Hd);
        float s = 0.f;
        for (int i = lane; i < Hd / 4; i += 32) {
            float4 a = ((const float4*)xs)[i];
            float4 b = wr[i];
            s += a.x * b.x + a.y * b.y + a.z * b.z + a.w * b.w;
        }
        #pragma unroll
        for (int o = 16; o; o >>= 1) s += __shfl_xor_sync(0xffffffffu, s, o);
        if (lane == 0) logits[e] = s;
    }
    __syncthreads();

    if (tid < Ee) g_combine[t * Ee + tid] = 0.f;
    __syncthreads();

    if (tid == 0) {
        float sc[Ee], sfc[Ee];
        for (int e = 0; e < Ee; e++) {
            float v = 1.f / (1.f + expf(-logits[e]));
            sc[e]  = v;
            sfc[e] = v + rb[e];
        }
        float gs[NGROUP];
        for (int g = 0; g < NGROUP; g++) {
            float m1 = -1e30f, m2 = -1e30f;
            for (int j = 0; j < GSZ; j++) {
                float v = sfc[g * GSZ + j];
                if (v > m1) { m2 = m1; m1 = v; }
                else if (v > m2) m2 = v;
            }
            gs[g] = m1 + m2;
        }
        bool gsel[NGROUP];
        for (int g = 0; g < NGROUP; g++) gsel[g] = false;
        for (int k = 0; k < TKG; k++) {
            int bi = -1; float bv = -1e30f;
            for (int g = 0; g < NGROUP; g++)
                if (!gsel[g] && gs[g] > bv) { bv = gs[g]; bi = g; }
            gsel[bi] = true;
        }
        float masked[Ee];
        for (int e = 0; e < Ee; e++) masked[e] = gsel[e / GSZ] ? sfc[e] : 0.0f;

        int   idx[TOPK]; float tw[TOPK]; float tsum = 0.f;
        for (int k = 0; k < TOPK; k++) {
            int bi = 0; float bv = -1e30f;
            for (int e = 0; e < Ee; e++)
                if (masked[e] > bv) { bv = masked[e]; bi = e; }
            masked[bi] = -1e30f;
            idx[k] = bi; tw[k] = sc[bi]; tsum += sc[bi];
        }
        float inv = SCALEF / (tsum + 1e-20f);
        for (int k = 0; k < TOPK; k++) {
            int e = idx[k];
            g_combine[t * Ee + e] = tw[k] * inv;
            int slot = atomicAdd(&g_cnt[e], 1);
            g_tok[e * Tt + slot] = t;
        }
    }
}

// ---------------- tf32 warp-mma GEMM: 128x256x32 block, 64x64 warp, cp.async x3 stages ----
#define BM 128
#define BN 256
#define BK 32
#define STAGES 3
#define NTHR 256
#define ASTR 36          // floats per A row (conflict-free frag reads)
#define BSTR 264         // floats per B row (conflict-free frag reads)
#define ASTAGE (BM * ASTR)   // 4608 floats
#define BSTAGE (BK * BSTR)   // 8448 floats
#define SMEM_BYTES (STAGES * (ASTAGE + BSTAGE) * 4)   // 156672

__device__ __forceinline__ uint32_t f2tf32(float f) {
    uint32_t r;
    asm("cvt.rna.tf32.f32 %0, %1;" : "=r"(r) : "f"(f));
    return r;
}

__device__ __forceinline__ void mma_tf32(float (&c)[4], const uint32_t (&a)[4],
                                         const uint32_t (&b)[2]) {
    asm volatile(
        "mma.sync.aligned.m16n8k8.row.col.f32.tf32.tf32.f32 "
        "{%0,%1,%2,%3}, {%4,%5,%6,%7}, {%8,%9}, {%0,%1,%2,%3};\n"
        : "+f"(c[0]), "+f"(c[1]), "+f"(c[2]), "+f"(c[3])
        : "r"(a[0]), "r"(a[1]), "r"(a[2]), "r"(a[3]), "r"(b[0]), "r"(b[1]));
}

__device__ __forceinline__ void cp16(uint32_t dst, const void* src, bool valid) {
    int sz = valid ? 16 : 0;
    asm volatile("cp.async.cg.shared.global [%0], [%1], 16, %2;\n"
                 :: "r"(dst), "l"(src), "r"(sz));
}
__device__ __forceinline__ void cp_commit() {
    asm volatile("cp.async.commit_group;\n");
}
__device__ __forceinline__ void cp_wait() {
    asm volatile("cp.async.wait_group %0;\n" :: "n"(STAGES - 2));
}

__device__ __forceinline__ void red2(float* p, float v0, float v1) {
    asm volatile("red.global.add.v2.f32 [%0], {%1,%2};\n" :: "l"(p), "f"(v0), "f"(v1));
}

// MODE 0: shared up   (A = x,        B = shared_up,   C = g_s1,  relu2)
// MODE 1: shared down (A = g_s1,     B = shared_down, C = out,   plain store)
// MODE 2: moe up      (A = x gather, B = w_up[e],     C = g_act, relu2*combine)
// MODE 3: moe down    (A = g_act,    B = w_down[e],   C = out,   atomic scatter)
template <int MODE>
__global__ __launch_bounds__(NTHR, 1)
void gemm_kernel(const float* __restrict__ Aglob, const float* __restrict__ Bglob,
                 float* __restrict__ Cglob) {
    extern __shared__ float smem[];
    float* As = smem;
    float* Bs = smem + STAGES * ASTAGE;

    constexpr int Kk = (MODE == 1) ? DS : ((MODE == 3) ? DF : Hd);
    constexpr int Nn = (MODE == 0) ? DS : ((MODE == 2) ? DF : Hd);

    const int tid = threadIdx.x;
    const int e  = (MODE >= 2) ? blockIdx.z : 0;
    const int m0 = blockIdx.y * BM;
    const int n0 = blockIdx.x * BN;

    int ne = Tt, off_e = 0;
    const float* Ap = Aglob;
    const float* Bp = Bglob;
    if (MODE == 1) Ap = g_s1;
    if (MODE == 3) Ap = g_act;
    if (MODE >= 2) {
        ne = g_cnt[e];
        if (m0 >= ne) return;
        off_e = g_off[e];
        Bp = Bglob + (size_t)e * Kk * Nn;
    }

    // ---- loader mapping (cp.async, 16B chunks) ----
    // A: 1024 chunks -> 4/thread; row = (tid>>3)+32i, col4 = (tid&7)*4
    const int ar0 = tid >> 3;
    const int ac4 = (tid & 7) * 4;
    const float* aSrc[4];
    #pragma unroll
    for (int i = 0; i < 4; i++) {
        int r = m0 + ar0 + i * 32;
        int grow;
        if (MODE == 2)      grow = (r < ne) ? g_tok[e * Tt + r] : -1;
        else if (MODE == 3) grow = (r < ne) ? (off_e + r) : -1;
        else                grow = r;
        aSrc[i] = (grow >= 0) ? (Ap + (size_t)grow * Kk + ac4) : nullptr;
    }
    uint32_t aDst = (uint32_t)__cvta_generic_to_shared(As) + (ar0 * ASTR + ac4) * 4;

    // B: 2048 chunks -> 8/thread; row = (tid>>6)+4i, col4 = (tid&63)*4
    const int br0 = tid >> 6;
    const int bc4 = (tid & 63) * 4;
    const float* bSrc = Bp + (size_t)br0 * Nn + n0 + bc4;
    uint32_t bDst = (uint32_t)__cvta_generic_to_shared(Bs) + (br0 * BSTR + bc4) * 4;

    auto issue = [&](int k0, int st) {
        uint32_t ad = aDst + st * (ASTAGE * 4);
        #pragma unroll
        for (int i = 0; i < 4; i++)
            cp16(ad + i * (32 * ASTR * 4),
                 aSrc[i] ? (aSrc[i] + k0) : Ap, aSrc[i] != nullptr);
        uint32_t bd = bDst + st * (BSTAGE * 4);
        const float* bp = bSrc + (size_t)k0 * Nn;
        #pragma unroll
        for (int i = 0; i < 8; i++)
            cp16(bd + i * (4 * BSTR * 4), bp + (size_t)i * 4 * Nn, true);
        cp_commit();
    };

    // ---- warp tiling: 2(m) x 4(n) warps, 64x64 per warp ----
    const int lane = tid & 31, wid = tid >> 5;
    const int qr = lane >> 2, qc = lane & 3;
    const int mb = (wid & 1) * 64;
    const int nb = (wid >> 1) * 64;

    float acc[4][8][4];
    #pragma unroll
    for (int mt = 0; mt < 4; mt++)
        #pragma unroll
        for (int nt = 0; nt < 8; nt++)
            #pragma unroll
            for (int j = 0; j < 4; j++) acc[mt][nt][j] = 0.f;

    const int nk = Kk / BK;

    #pragma unroll
    for (int s = 0; s < STAGES - 1; s++) issue(s * BK, s);

    for (int kb = 0; kb < nk; kb++) {
        cp_wait();
        __syncthreads();

        if (kb + STAGES - 1 < nk) issue((kb + STAGES - 1) * BK, (kb + STAGES - 1) % STAGES);
        else                      cp_commit();   // keep group counts aligned

        const uint32_t* Au = (const uint32_t*)(As + (kb % STAGES) * ASTAGE);
        const uint32_t* Bu = (const uint32_t*)(Bs + (kb % STAGES) * BSTAGE);

        #pragma unroll
        for (int ks = 0; ks < BK; ks += 8) {
            uint32_t a[4][4], b[8][2];
            #pragma unroll
            for (int mt = 0; mt < 4; mt++) {
                int r  = mb + mt * 16 + qr;
                int kc = ks + qc;
                a[mt][0] = f2tf32(__uint_as_float(Au[r * ASTR + kc]));
                a[mt][1] = f2tf32(__uint_as_float(Au[(r + 8) * ASTR + kc]));
                a[mt][2] = f2tf32(__uint_as_float(Au[r * ASTR + kc + 4]));
                a[mt][3] = f2tf32(__uint_as_float(Au[(r + 8) * ASTR + kc + 4]));
            }
            #pragma unroll
            for (int nt = 0; nt < 8; nt++) {
                int n = nb + nt * 8 + qr;
                b[nt][0] = f2tf32(__uint_as_float(Bu[(ks + qc) * BSTR + n]));
                b[nt][1] = f2tf32(__uint_as_float(Bu[(ks + qc + 4) * BSTR + n]));
            }
            #pragma unroll
            for (int mt = 0; mt < 4; mt++)
                #pragma unroll
                for (int nt = 0; nt < 8; nt++)
                    mma_tf32(acc[mt][nt], a[mt], b[nt]);
        }
        __syncthreads();
    }

    // -------- epilogue --------
    #pragma unroll
    for (int mt = 0; mt < 4; mt++) {
        int rl0 = mb + mt * 16 + qr;
        int rl1 = rl0 + 8;
        if (MODE == 0 || MODE == 1) {
            int r0 = m0 + rl0, r1 = m0 + rl1;
            float* Cb = (MODE == 0) ? g_s1 : Cglob;
            #pragma unroll
            for (int nt = 0; nt < 8; nt++) {
                int c = n0 + nb + nt * 8 + qc * 2;
                float v0 = acc[mt][nt][0], v1 = acc[mt][nt][1];
                float v2 = acc[mt][nt][2], v3 = acc[mt][nt][3];
                if (MODE == 0) {
                    v0 = fmaxf(v0, 0.f); v0 *= v0;
                    v1 = fmaxf(v1, 0.f); v1 *= v1;
                    v2 = fmaxf(v2, 0.f); v2 *= v2;
                    v3 = fmaxf(v3, 0.f); v3 *= v3;
                }
                *(float2*)&Cb[(size_t)r0 * Nn + c] = make_float2(v0, v1);
                *(float2*)&Cb[(size_t)r1 * Nn + c] = make_float2(v2, v3);
            }
        } else if (MODE == 2) {
            bool va = (m0 + rl0) < ne, vb = (m0 + rl1) < ne;
            int tk0 = va ? g_tok[e * Tt + m0 + rl0] : 0;
            int tk1 = vb ? g_tok[e * Tt + m0 + rl1] : 0;
            float w0 = va ? g_combine[tk0 * Ee + e] : 0.f;
            float w1 = vb ? g_combine[tk1 * Ee + e] : 0.f;
            size_t cr0 = (size_t)(off_e + m0 + rl0) * DF;
            size_t cr1 = (size_t)(off_e + m0 + rl1) * DF;
            #pragma unroll
            for (int nt = 0; nt < 8; nt++) {
                int c = n0 + nb + nt * 8 + qc * 2;
                float v0 = fmaxf(acc[mt][nt][0], 0.f); v0 = v0 * v0 * w0;
                float v1 = fmaxf(acc[mt][nt][1], 0.f); v1 = v1 * v1 * w0;
                float v2 = fmaxf(acc[mt][nt][2], 0.f); v2 = v2 * v2 * w1;
                float v3 = fmaxf(acc[mt][nt][3], 0.f); v3 = v3 * v3 * w1;
                if (va) *(float2*)&g_act[cr0 + c] = make_float2(v0, v1);
                if (vb) *(float2*)&g_act[cr1 + c] = make_float2(v2, v3);
            }
        } else {  // MODE 3: vector atomic scatter into out
            bool va = (m0 + rl0) < ne, vb = (m0 + rl1) < ne;
            int tk0 = va ? g_tok[e * Tt + m0 + rl0] : 0;
            int tk1 = vb ? g_tok[e * Tt + m0 + rl1] : 0;
            #pragma unroll
            for (int nt = 0; nt < 8; nt++) {
                int c = n0 + nb + nt * 8 + qc * 2;
                if (va) red2(&Cglob[(size_t)tk0 * Hd + c], acc[mt][nt][0], acc[mt][nt][1]);
                if (vb) red2(&Cglob[(size_t)tk1 * Hd + c], acc[mt][nt][2], acc[mt][nt][3]);
            }
        }
    }
}

// ---------------- launch ----------------
extern "C" void kernel_launch(void* const* d_in, const int* in_sizes, int n_in,
                              void* d_out, int out_size) {
    const float* x     = (const float*)d_in[0];
    const float* rw    = (const float*)d_in[1];
    const float* rb    = (const float*)d_in[2];
    const float* w_up  = (const float*)d_in[3];
    const float* w_dn  = (const float*)d_in[4];
    const float* s_up  = (const float*)d_in[5];
    const float* s_dn  = (const float*)d_in[6];
    float* out = (float*)d_out;

    cudaFuncSetAttribute(gemm_kernel<0>, cudaFuncAttributeMaxDynamicSharedMemorySize, SMEM_BYTES);
    cudaFuncSetAttribute(gemm_kernel<1>, cudaFuncAttributeMaxDynamicSharedMemorySize, SMEM_BYTES);
    cudaFuncSetAttribute(gemm_kernel<2>, cudaFuncAttributeMaxDynamicSharedMemorySize, SMEM_BYTES);
    cudaFuncSetAttribute(gemm_kernel<3>, cudaFuncAttributeMaxDynamicSharedMemorySize, SMEM_BYTES);

    zero_cnt_kernel<<<1, 32>>>();
    router_kernel<<<Tt, 128>>>(x, rw, rb);
    offs_kernel<<<1, 32>>>();

    // routed up: per-expert gathered GEMM -> g_act
    gemm_kernel<2><<<dim3(DF / BN, Tt / BM, Ee), NTHR, SMEM_BYTES>>>(x, w_up, nullptr);

    // shared expert
    gemm_kernel<0><<<dim3(DS / BN, Tt / BM, 1), NTHR, SMEM_BYTES>>>(x, s_up, nullptr);
    gemm_kernel<1><<<dim3(Hd / BN, Tt / BM, 1), NTHR, SMEM_BYTES>>>(nullptr, s_dn, out);

    // routed down: atomic scatter onto out (after shared wrote it)
    gemm_kernel<3><<<dim3(Hd / BN, Tt / BM, Ee), NTHR, SMEM_BYTES>>>(nullptr, w_dn, out);
}